// round 3
// baseline (speedup 1.0000x reference)
#include <cuda_runtime.h>
#include <math.h>

#define BATCH   1048576
#define NANCH   3
#define NGT     8
#define NTHREAD (BATCH * NANCH)
#define TPB     256
#define NBLK    (NTHREAD / TPB)       // 12288
#define LAMBDA_COORD 5.0f

__device__ double       g_acc   = 0.0;
__device__ unsigned int g_count = 0u;

__global__ void __launch_bounds__(TPB) yolo_loss_kernel(
    const float4* __restrict__ pred4,   // (B, 3, 8) floats -> 2 float4 per anchor
    const float4* __restrict__ gtb4,    // (B, 8, 4) floats -> 8 float4 per row
    const int*    __restrict__ gtc,     // (B, 8) ints
    float*        __restrict__ out)
{
    const int idx = blockIdx.x * blockDim.x + threadIdx.x;   // (row, anchor)
    const int row = idx / 3;

    // ---- per-anchor prediction ----
    const float4 p0 = pred4[(size_t)idx * 2 + 0];
    const float4 p1 = pred4[(size_t)idx * 2 + 1];

    const float px = __fdividef(1.0f, 1.0f + __expf(-p0.x));
    const float py = __fdividef(1.0f, 1.0f + __expf(-p0.y));
    const float pw = p0.z;
    const float ph = p0.w;
    const float xc = p1.x;                 // raw conf logit
    const float l0 = p1.y, l1 = p1.z, l2 = p1.w;

    const float px1 = px - pw * 0.5f;
    const float px2 = px + pw * 0.5f;
    const float py1 = py - ph * 0.5f;
    const float py2 = py + ph * 0.5f;
    const float parea = (px2 - px1) * (py2 - py1);

    // ---- stream 8 gt boxes, division-free first-occurrence argmax ----
    const size_t gbase = (size_t)row * NGT;
    float best_inter, best_den;
    float bx, by, bw, bh;
    int   bestj = 0;

    {
        const float4 g0 = gtb4[gbase];
        const float gw = g0.z, gh = g0.w;
        const float gx1 = g0.x - gw * 0.5f, gx2 = g0.x + gw * 0.5f;
        const float gy1 = g0.y - gh * 0.5f, gy2 = g0.y + gh * 0.5f;
        const float iw = fmaxf(fminf(px2, gx2) - fmaxf(px1, gx1), 0.0f);
        const float ih = fmaxf(fminf(py2, gy2) - fmaxf(py1, gy1), 0.0f);
        best_inter = iw * ih;
        best_den   = parea + (gx2 - gx1) * (gy2 - gy1) - best_inter + 1e-6f;
        bx = g0.x; by = g0.y; bw = gw; bh = gh;
    }

    #pragma unroll
    for (int j = 1; j < NGT; ++j) {
        const float4 g = gtb4[gbase + j];
        const float gw = g.z, gh = g.w;
        const float gx1 = g.x - gw * 0.5f, gx2 = g.x + gw * 0.5f;
        const float gy1 = g.y - gh * 0.5f, gy2 = g.y + gh * 0.5f;
        const float iw = fmaxf(fminf(px2, gx2) - fmaxf(px1, gx1), 0.0f);
        const float ih = fmaxf(fminf(py2, gy2) - fmaxf(py1, gy1), 0.0f);
        const float inter = iw * ih;
        const float den   = parea + (gx2 - gx1) * (gy2 - gy1) - inter + 1e-6f;
        // iou_j > iou_best  <=>  (inter*best_den - best_inter*den) * (den*best_den) > 0
        const float diff = inter * best_den - best_inter * den;
        const float sgn  = den * best_den;
        if (diff * sgn > 0.0f) {
            best_inter = inter; best_den = den;
            bx = g.x; by = g.y; bw = gw; bh = gh;
            bestj = j;
        }
    }

    const bool matched = (best_den > 0.0f) && (2.0f * best_inter > best_den);

    // ---- conf loss: softplus of (+/-) raw logit, clamped at 100 ----
    const float t  = matched ? -xc : xc;
    const float sp = fmaxf(t, 0.0f) + __logf(1.0f + __expf(-fabsf(t)));
    float lsum = fminf(sp, 100.0f);

    if (matched) {
        const float dx = px - bx, dy = py - by, dw = pw - bw, dh = ph - bh;
        lsum += LAMBDA_COORD * (dx * dx + dy * dy + dw * dw + dh * dh);
        const int   c   = gtc[gbase + bestj];
        const float mx  = fmaxf(l0, fmaxf(l1, l2));
        const float lse = mx + __logf(__expf(l0 - mx) + __expf(l1 - mx) + __expf(l2 - mx));
        const float lc  = (c == 0) ? l0 : ((c == 1) ? l1 : l2);
        lsum += lse - lc;
    }

    // ---- block reduction ----
    #pragma unroll
    for (int o = 16; o > 0; o >>= 1)
        lsum += __shfl_down_sync(0xFFFFFFFFu, lsum, o);

    __shared__ float ssum[TPB / 32];
    __shared__ bool  s_last;
    const int lane = threadIdx.x & 31;
    const int wid  = threadIdx.x >> 5;
    if (lane == 0) ssum[wid] = lsum;
    __syncthreads();

    if (threadIdx.x == 0) {
        float v = 0.0f;
        #pragma unroll
        for (int w = 0; w < TPB / 32; ++w) v += ssum[w];

        atomicAdd(&g_acc, (double)v);          // RED.ADD, result unused
        __threadfence();
        const unsigned int ticket = atomicAdd(&g_count, 1u);
        s_last = (ticket == (unsigned int)(NBLK - 1));
    }
    __syncthreads();

    // ---- last block finalizes: read accumulator, write output, reset ----
    if (s_last && threadIdx.x == 0) {
        const double acc = atomicAdd(&g_acc, 0.0);   // coherent read
        out[0] = (float)(acc / (double)BATCH);
        // reset for next graph replay (kernel boundary orders this)
        atomicExch((unsigned long long*)&g_acc, 0ull);
        atomicExch(&g_count, 0u);
    }
}

extern "C" void kernel_launch(void* const* d_in, const int* in_sizes, int n_in,
                              void* d_out, int out_size) {
    const float4* pred4 = (const float4*)d_in[0];
    const float4* gtb4  = (const float4*)d_in[1];
    const int*    gtc   = (const int*)d_in[2];
    float* out = (float*)d_out;

    yolo_loss_kernel<<<NBLK, TPB>>>(pred4, gtb4, gtc, out);
}

// round 4
// speedup vs baseline: 1.2749x; 1.2749x over previous
#include <cuda_runtime.h>
#include <math.h>

#define BATCH   1048576
#define NANCH   3
#define NGT     8
#define NTHREAD (BATCH * NANCH)
#define TPB     384                    // 128 rows per block (384/3)
#define ROWS_PB (TPB / NANCH)          // 128
#define NBLK    (NTHREAD / TPB)        // 8192
#define GT_PAD  9                      // float4 per row in smem (pad 8->9 breaks bank aliasing)
#define LAMBDA_COORD 5.0f

__device__ double g_acc = 0.0;

__global__ void __launch_bounds__(TPB) yolo_loss_kernel(
    const float4* __restrict__ pred4,   // (B, 3, 8) floats -> 2 float4 per anchor
    const float4* __restrict__ gtb4,    // (B, 8, 4) floats -> 8 float4 per row
    const int*    __restrict__ gtc)     // (B, 8) ints
{
    __shared__ float4 sgt[ROWS_PB * GT_PAD];     // 18 KB
    __shared__ float  ssum[TPB / 32];

    const int tid = threadIdx.x;

    // ---- cooperative, coalesced stage of gt boxes for this block's 128 rows ----
    {
        const size_t gbase4 = (size_t)blockIdx.x * (ROWS_PB * NGT);   // float4 index
        #pragma unroll
        for (int i = tid; i < ROWS_PB * NGT; i += TPB) {
            const int r = i >> 3;
            const int j = i & 7;
            sgt[r * GT_PAD + j] = gtb4[gbase4 + i];
        }
    }
    __syncthreads();

    // ---- per-anchor prediction ----
    const int idx  = blockIdx.x * TPB + tid;   // (row, anchor)
    const int rloc = tid / 3;                  // local row 0..127

    const float4 p0 = pred4[(size_t)idx * 2 + 0];
    const float4 p1 = pred4[(size_t)idx * 2 + 1];

    const float px = __fdividef(1.0f, 1.0f + __expf(-p0.x));
    const float py = __fdividef(1.0f, 1.0f + __expf(-p0.y));
    const float pw = p0.z;
    const float ph = p0.w;
    const float xc = p1.x;                     // raw conf logit
    const float l0 = p1.y, l1 = p1.z, l2 = p1.w;

    const float px1 = px - pw * 0.5f;
    const float px2 = px + pw * 0.5f;
    const float py1 = py - ph * 0.5f;
    const float py2 = py + ph * 0.5f;
    const float parea = (px2 - px1) * (py2 - py1);

    // ---- 8 gt boxes from smem, division-free first-occurrence argmax ----
    const float4* grow = &sgt[rloc * GT_PAD];
    float best_inter, best_den;
    float bx, by, bw, bh;
    int   bestj = 0;

    {
        const float4 g0 = grow[0];
        const float gw = g0.z, gh = g0.w;
        const float gx1 = g0.x - gw * 0.5f, gx2 = g0.x + gw * 0.5f;
        const float gy1 = g0.y - gh * 0.5f, gy2 = g0.y + gh * 0.5f;
        const float iw = fmaxf(fminf(px2, gx2) - fmaxf(px1, gx1), 0.0f);
        const float ih = fmaxf(fminf(py2, gy2) - fmaxf(py1, gy1), 0.0f);
        best_inter = iw * ih;
        best_den   = parea + (gx2 - gx1) * (gy2 - gy1) - best_inter + 1e-6f;
        bx = g0.x; by = g0.y; bw = gw; bh = gh;
    }

    #pragma unroll
    for (int j = 1; j < NGT; ++j) {
        const float4 g = grow[j];
        const float gw = g.z, gh = g.w;
        const float gx1 = g.x - gw * 0.5f, gx2 = g.x + gw * 0.5f;
        const float gy1 = g.y - gh * 0.5f, gy2 = g.y + gh * 0.5f;
        const float iw = fmaxf(fminf(px2, gx2) - fmaxf(px1, gx1), 0.0f);
        const float ih = fmaxf(fminf(py2, gy2) - fmaxf(py1, gy1), 0.0f);
        const float inter = iw * ih;
        const float den   = parea + (gx2 - gx1) * (gy2 - gy1) - inter + 1e-6f;
        // iou_j > iou_best  <=>  (inter*best_den - best_inter*den) * (den*best_den) > 0
        const float diff = inter * best_den - best_inter * den;
        const float sgn  = den * best_den;
        if (diff * sgn > 0.0f) {
            best_inter = inter; best_den = den;
            bx = g.x; by = g.y; bw = gw; bh = gh;
            bestj = j;
        }
    }

    const bool matched = (best_den > 0.0f) && (2.0f * best_inter > best_den);

    // ---- conf loss: softplus of (+/-) raw logit, clamped at 100 ----
    const float t  = matched ? -xc : xc;
    const float sp = fmaxf(t, 0.0f) + __logf(1.0f + __expf(-fabsf(t)));
    float lsum = fminf(sp, 100.0f);

    if (matched) {
        const float dx = px - bx, dy = py - by, dw = pw - bw, dh = ph - bh;
        lsum += LAMBDA_COORD * (dx * dx + dy * dy + dw * dw + dh * dh);
        const int   c   = gtc[(size_t)(idx / 3) * NGT + bestj];
        const float mx  = fmaxf(l0, fmaxf(l1, l2));
        const float lse = mx + __logf(__expf(l0 - mx) + __expf(l1 - mx) + __expf(l2 - mx));
        const float lc  = (c == 0) ? l0 : ((c == 1) ? l1 : l2);
        lsum += lse - lc;
    }

    // ---- block reduction -> one fire-and-forget double RED per block ----
    #pragma unroll
    for (int o = 16; o > 0; o >>= 1)
        lsum += __shfl_down_sync(0xFFFFFFFFu, lsum, o);

    const int lane = tid & 31;
    const int wid  = tid >> 5;
    if (lane == 0) ssum[wid] = lsum;
    __syncthreads();

    if (tid == 0) {
        float v = 0.0f;
        #pragma unroll
        for (int w = 0; w < TPB / 32; ++w) v += ssum[w];
        atomicAdd(&g_acc, (double)v);          // RED.ADD, no return, no fence
    }
}

__global__ void finalize_kernel(float* __restrict__ out) {
    out[0] = (float)(g_acc / (double)BATCH);
    g_acc  = 0.0;                              // reset for next graph replay
}

extern "C" void kernel_launch(void* const* d_in, const int* in_sizes, int n_in,
                              void* d_out, int out_size) {
    const float4* pred4 = (const float4*)d_in[0];
    const float4* gtb4  = (const float4*)d_in[1];
    const int*    gtc   = (const int*)d_in[2];
    float* out = (float*)d_out;

    yolo_loss_kernel<<<NBLK, TPB>>>(pred4, gtb4, gtc);
    finalize_kernel<<<1, 1>>>(out);
}

// round 5
// speedup vs baseline: 1.4264x; 1.1188x over previous
#include <cuda_runtime.h>
#include <math.h>

#define BATCH   1048576
#define NANCH   3
#define NGT     8
#define NTHREAD (BATCH * NANCH)
#define TPB     384                    // 128 rows per block (384/3)
#define ROWS_PB (TPB / NANCH)          // 128
#define NBLK    (NTHREAD / TPB)        // 8192
#define GT_PAD  9                      // float4 per row in smem (pad 8->9 breaks bank aliasing)
#define LAMBDA_COORD 5.0f

__device__ double g_acc = 0.0;

__global__ void __launch_bounds__(TPB, 4) yolo_loss_kernel(
    const float4* __restrict__ pred4,   // (B, 3, 8) floats -> 2 float4 per anchor
    const float4* __restrict__ gtb4,    // (B, 8, 4) floats -> 8 float4 per row
    const int*    __restrict__ gtc)     // (B, 8) ints
{
    __shared__ float4 sgt[ROWS_PB * GT_PAD];     // 18 KB
    __shared__ float  ssum[TPB / 32];

    const int tid = threadIdx.x;

    // ---- cooperative, coalesced stage of gt boxes for this block's 128 rows ----
    {
        const size_t gbase4 = (size_t)blockIdx.x * (ROWS_PB * NGT);   // float4 index
        #pragma unroll
        for (int i = tid; i < ROWS_PB * NGT; i += TPB) {
            const int r = i >> 3;
            const int j = i & 7;
            sgt[r * GT_PAD + j] = gtb4[gbase4 + i];
        }
    }
    __syncthreads();

    // ---- per-anchor prediction ----
    const int idx  = blockIdx.x * TPB + tid;   // (row, anchor)
    const int rloc = tid / 3;                  // local row 0..127

    const float4 p0 = pred4[(size_t)idx * 2 + 0];
    const float4 p1 = pred4[(size_t)idx * 2 + 1];

    const float px = __fdividef(1.0f, 1.0f + __expf(-p0.x));
    const float py = __fdividef(1.0f, 1.0f + __expf(-p0.y));
    const float pw = p0.z;
    const float ph = p0.w;
    const float xc = p1.x;                     // raw conf logit
    const float l0 = p1.y, l1 = p1.z, l2 = p1.w;

    const float px1 = px - pw * 0.5f;
    const float px2 = px + pw * 0.5f;
    const float py1 = py - ph * 0.5f;
    const float py2 = py + ph * 0.5f;
    const float parea = (px2 - px1) * (py2 - py1);

    // ---- 8 gt boxes from smem, division-free first-occurrence argmax ----
    const float4* grow = &sgt[rloc * GT_PAD];
    float best_inter, best_den;
    float bx, by, bw, bh;
    int   bestj = 0;

    {
        const float4 g0 = grow[0];
        const float gw = g0.z, gh = g0.w;
        const float gx1 = g0.x - gw * 0.5f, gx2 = g0.x + gw * 0.5f;
        const float gy1 = g0.y - gh * 0.5f, gy2 = g0.y + gh * 0.5f;
        const float iw = fmaxf(fminf(px2, gx2) - fmaxf(px1, gx1), 0.0f);
        const float ih = fmaxf(fminf(py2, gy2) - fmaxf(py1, gy1), 0.0f);
        best_inter = iw * ih;
        best_den   = parea + (gx2 - gx1) * (gy2 - gy1) - best_inter + 1e-6f;
        bx = g0.x; by = g0.y; bw = gw; bh = gh;
    }

    #pragma unroll
    for (int j = 1; j < NGT; ++j) {
        const float4 g = grow[j];
        const float gw = g.z, gh = g.w;
        const float gx1 = g.x - gw * 0.5f, gx2 = g.x + gw * 0.5f;
        const float gy1 = g.y - gh * 0.5f, gy2 = g.y + gh * 0.5f;
        const float iw = fmaxf(fminf(px2, gx2) - fmaxf(px1, gx1), 0.0f);
        const float ih = fmaxf(fminf(py2, gy2) - fmaxf(py1, gy1), 0.0f);
        const float inter = iw * ih;
        const float den   = parea + (gx2 - gx1) * (gy2 - gy1) - inter + 1e-6f;
        // iou_j > iou_best  <=>  (inter*best_den - best_inter*den) * (den*best_den) > 0
        const float diff = inter * best_den - best_inter * den;
        const float sgn  = den * best_den;
        if (diff * sgn > 0.0f) {
            best_inter = inter; best_den = den;
            bx = g.x; by = g.y; bw = gw; bh = gh;
            bestj = j;
        }
    }

    const bool matched = (best_den > 0.0f) && (2.0f * best_inter > best_den);

    // ---- conf loss: softplus of (+/-) raw logit, clamped at 100 ----
    const float t  = matched ? -xc : xc;
    const float sp = fmaxf(t, 0.0f) + __logf(1.0f + __expf(-fabsf(t)));
    float lsum = fminf(sp, 100.0f);

    if (matched) {
        const float dx = px - bx, dy = py - by, dw = pw - bw, dh = ph - bh;
        lsum += LAMBDA_COORD * (dx * dx + dy * dy + dw * dw + dh * dh);
        const int   c   = gtc[(size_t)(idx / 3) * NGT + bestj];
        const float mx  = fmaxf(l0, fmaxf(l1, l2));
        const float lse = mx + __logf(__expf(l0 - mx) + __expf(l1 - mx) + __expf(l2 - mx));
        const float lc  = (c == 0) ? l0 : ((c == 1) ? l1 : l2);
        lsum += lse - lc;
    }

    // ---- block reduction -> one fire-and-forget double RED per block ----
    #pragma unroll
    for (int o = 16; o > 0; o >>= 1)
        lsum += __shfl_down_sync(0xFFFFFFFFu, lsum, o);

    const int lane = tid & 31;
    const int wid  = tid >> 5;
    if (lane == 0) ssum[wid] = lsum;
    __syncthreads();

    if (tid == 0) {
        float v = 0.0f;
        #pragma unroll
        for (int w = 0; w < TPB / 32; ++w) v += ssum[w];
        atomicAdd(&g_acc, (double)v);          // RED.ADD, no return, no fence
    }

    // allow the dependent finalize kernel's launch to overlap our drain
    cudaTriggerProgrammaticLaunchCompletion();
}

__global__ void finalize_kernel(float* __restrict__ out) {
    cudaGridDependencySynchronize();           // wait for all REDs to be visible
    out[0] = (float)(g_acc / (double)BATCH);
    g_acc  = 0.0;                              // reset for next graph replay
}

extern "C" void kernel_launch(void* const* d_in, const int* in_sizes, int n_in,
                              void* d_out, int out_size) {
    const float4* pred4 = (const float4*)d_in[0];
    const float4* gtb4  = (const float4*)d_in[1];
    const int*    gtc   = (const int*)d_in[2];
    float* out = (float*)d_out;

    yolo_loss_kernel<<<NBLK, TPB>>>(pred4, gtb4, gtc);

    // PDL: finalize launches while the main grid drains; the device-side
    // cudaGridDependencySynchronize() provides the ordering.
    cudaLaunchConfig_t cfg = {};
    cfg.gridDim  = dim3(1, 1, 1);
    cfg.blockDim = dim3(1, 1, 1);
    cudaLaunchAttribute attr[1];
    attr[0].id = cudaLaunchAttributeProgrammaticStreamSerialization;
    attr[0].val.programmaticStreamSerializationAllowed = 1;
    cfg.attrs    = attr;
    cfg.numAttrs = 1;
    cudaLaunchKernelEx(&cfg, finalize_kernel, out);
}